// round 10
// baseline (speedup 1.0000x reference)
#include <cuda_runtime.h>
#include <cuda_fp16.h>
#include <cstdint>

#define KDIM 4096
#define ODIM 11008
#define KW   1376            // ODIM/8
#define BM 128
#define BN 128
#define NSTG 64              // KDIM/64
#define NK16 256             // KDIM/16

#define STG 16384            // B only: 128 rows x 128B
#define SMEM_TOTAL 49152     // 3 stages

__device__ uint4  g_xq[(size_t)256 * 256 * 32];   // A fragment-direct blocked layout
__device__ __half g_w16[(size_t)11008 * 4096];    // dequant weights fp16, [O][K]

// ---- pre-kernel 1: x fp32 -> fp16 fragment-direct layout ----
// tile (m16,k16): lane L holds 16B = {a0,a1,a2,a3} halves pairs:
// a0=(m16*16+r, k16*16+c2), a1=(+8 row), a2=(row, k+8), a3=(row+8, k+8)
__global__ __launch_bounds__(256)
void cvt_xq(const float* __restrict__ x) {
    const int w    = threadIdx.x >> 5;
    const int lane = threadIdx.x & 31;
    const int ti   = blockIdx.x * 8 + w;        // 0..65535
    const int m16  = ti >> 8;
    const int k16  = ti & 255;
    const int r  = lane >> 2;
    const int c2 = (lane & 3) * 2;
    const size_t row0 = (size_t)(m16 * 16 + r) * KDIM;
    const size_t row1 = row0 + 8 * KDIM;
    const int k0 = k16 * 16 + c2;
    float2 v00 = *(const float2*)(x + row0 + k0);
    float2 v10 = *(const float2*)(x + row1 + k0);
    float2 v01 = *(const float2*)(x + row0 + k0 + 8);
    float2 v11 = *(const float2*)(x + row1 + k0 + 8);
    __half2 h0 = __floats2half2_rn(v00.x, v00.y);
    __half2 h1 = __floats2half2_rn(v10.x, v10.y);
    __half2 h2 = __floats2half2_rn(v01.x, v01.y);
    __half2 h3 = __floats2half2_rn(v11.x, v11.y);
    g_xq[(size_t)ti * 32 + lane] =
        make_uint4(*(unsigned*)&h0, *(unsigned*)&h1, *(unsigned*)&h2, *(unsigned*)&h3);
}

// ------- pre-kernel 2: dequantize weights to fp16 [O][K] (unchanged) -------
__global__ __launch_bounds__(256)
void dequant_w(const int* __restrict__ qweight, const float* __restrict__ scales,
               const int* __restrict__ qzeros) {
    const int w  = blockIdx.x * 32 + (threadIdx.x & 31);
    const int kb = blockIdx.y * 8  + (threadIdx.x >> 5);
    const int g  = kb >> 3;

    int qw[16];
    #pragma unroll
    for (int i = 0; i < 16; i++)
        qw[i] = qweight[(size_t)(kb * 16 + i) * KW + w];
    const int zw = qzeros[(size_t)g * KW + w];
    const float4 s0 = *(const float4*)(scales + (size_t)g * ODIM + w * 8);
    const float4 s1 = *(const float4*)(scales + (size_t)g * ODIM + w * 8 + 4);
    const float sv[8] = {s0.x, s0.y, s0.z, s0.w, s1.x, s1.y, s1.z, s1.w};

    #pragma unroll
    for (int j = 0; j < 8; j++) {
        const int z = (zw >> (4 * j)) & 15;
        const float s = sv[j];
        unsigned u[8];
        #pragma unroll
        for (int p = 0; p < 8; p++) {
            float f0 = (float)(((qw[2 * p]     >> (4 * j)) & 15) - z) * s;
            float f1 = (float)(((qw[2 * p + 1] >> (4 * j)) & 15) - z) * s;
            __half2 h = __floats2half2_rn(f0, f1);
            u[p] = *(unsigned*)&h;
        }
        __half* dst = g_w16 + (size_t)(w * 8 + j) * KDIM + kb * 16;
        *(uint4*)dst       = make_uint4(u[0], u[1], u[2], u[3]);
        *(uint4*)(dst + 8) = make_uint4(u[4], u[5], u[6], u[7]);
    }
}

// ---------------- helpers ----------------
#define CP16(dst, src) \
    asm volatile("cp.async.cg.shared.global [%0], [%1], 16;" :: "r"(dst), "l"(src))

static __device__ __forceinline__ void ldsm_x4(unsigned* r, unsigned addr) {
    asm volatile("ldmatrix.sync.aligned.m8n8.x4.shared.b16 {%0,%1,%2,%3}, [%4];"
                 : "=r"(r[0]), "=r"(r[1]), "=r"(r[2]), "=r"(r[3]) : "r"(addr));
}
static __device__ __forceinline__ void mma_f16(float* c, const unsigned* a,
                                               const unsigned* b) {
    asm volatile(
        "mma.sync.aligned.m16n8k16.row.col.f32.f16.f16.f32 "
        "{%0,%1,%2,%3}, {%4,%5,%6,%7}, {%8,%9}, {%0,%1,%2,%3};"
        : "+f"(c[0]), "+f"(c[1]), "+f"(c[2]), "+f"(c[3])
        : "r"(a[0]), "r"(a[1]), "r"(a[2]), "r"(a[3]), "r"(b[0]), "r"(b[1]));
}

// -- main GEMM: 128 thr, 4 warps 2x2, warp 64x64; A direct from L2, B via smem --
__global__ __launch_bounds__(128, 2)
void w4_hgemm(float* __restrict__ out) {
    extern __shared__ char smem[];
    const int tid  = threadIdx.x;
    const int lane = tid & 31;
    const int wid  = tid >> 5;
    const int wm   = wid >> 1;                 // 0..1  (64 rows)
    const int wn   = wid & 1;                  // 0..1  (64 cols)
    const int bm0  = blockIdx.x * BM;          // bm fast
    const int bn0  = blockIdx.y * BN;

    const char*  gb = (const char*)(g_w16 + (size_t)bn0 * KDIM);
    // A frag base for this warp: m16 = bm0/16 + wm*4 + mt, lane fixed
    const uint4* gaq = g_xq + ((size_t)(bm0 / 16 + wm * 4) * NK16) * 32 + lane;

    float acc[4][8][4];
    #pragma unroll
    for (int i = 0; i < 4; i++)
        #pragma unroll
        for (int j = 0; j < 8; j++)
            #pragma unroll
            for (int q = 0; q < 4; q++) acc[i][j][q] = 0.0f;

    auto issueB = [&](int t) {
        char* s = smem + (t % 3) * STG;
        #pragma unroll
        for (int i = 0; i < 8; i++) {            // B: 1024 16B chunks
            const int idx = tid + 128 * i;
            const int n  = idx >> 3;             // 0..127
            const int ch = idx & 7;
            unsigned d = (unsigned)__cvta_generic_to_shared(
                s + n * 128 + ((ch ^ (n & 7)) * 16));
            CP16(d, gb + (size_t)n * 8192 + (size_t)t * 128 + ch * 16);
        }
        asm volatile("cp.async.commit_group;");
    };

    issueB(0);
    issueB(1);

    const int bg = lane >> 3;                    // 0..3 B matrix group

    // A frag load: (mt, k16) -> uint4
    auto ldA = [&](int mt, int k16) {
        return gaq[((size_t)mt * NK16 + k16) * 32];
    };

    uint4 a_cur[4], a_nxt[4];
    #pragma unroll
    for (int mt = 0; mt < 4; mt++) a_cur[mt] = ldA(mt, 0);   // (t0,ks0)

    #pragma unroll 1
    for (int t = 0; t < NSTG; t++) {
        if (t + 1 < NSTG) asm volatile("cp.async.wait_group 1;");
        else              asm volatile("cp.async.wait_group 0;");
        __syncthreads();
        if (t + 2 < NSTG) issueB(t + 2);

        const char* Bs = smem + (t % 3) * STG;

        #pragma unroll
        for (int ks = 0; ks < 4; ks++) {         // 4 x k16 steps
            // prefetch next A frags (global, no barrier dependency)
            const int nk16 = t * 4 + ks + 1;
            if (nk16 < NK16) {
                #pragma unroll
                for (int mt = 0; mt < 4; mt++) a_nxt[mt] = ldA(mt, nk16);
            }
            unsigned b[8][2];
            #pragma unroll
            for (int p = 0; p < 4; p++) {        // each x4 fills frags 2p, 2p+1
                const int n  = wn * 64 + p * 16 + ((bg >> 1) << 3) + (lane & 7);
                const int ch = 2 * ks + (bg & 1);
                ldsm_x4(&b[2 * p][0], (unsigned)__cvta_generic_to_shared(
                    Bs + n * 128 + ((ch ^ (n & 7)) * 16)));
            }
            #pragma unroll
            for (int mt = 0; mt < 4; mt++)
                #pragma unroll
                for (int nt = 0; nt < 8; nt++)
                    mma_f16(acc[mt][nt], (const unsigned*)&a_cur[mt], b[nt]);
            #pragma unroll
            for (int mt = 0; mt < 4; mt++) a_cur[mt] = a_nxt[mt];
        }
    }

    // ---- epilogue: streaming stores ----
    const int r = lane >> 2;
    const int c = lane & 3;
    #pragma unroll
    for (int mt = 0; mt < 4; mt++) {
        #pragma unroll
        for (int nt = 0; nt < 8; nt++) {
            const int row = bm0 + wm * 64 + mt * 16 + r;
            const int col = bn0 + wn * 64 + nt * 8 + c * 2;
            float* p = out + (size_t)row * ODIM + col;
            __stcs((float2*)p, make_float2(acc[mt][nt][0], acc[mt][nt][1]));
            __stcs((float2*)(p + (size_t)8 * ODIM),
                   make_float2(acc[mt][nt][2], acc[mt][nt][3]));
        }
    }
}

extern "C" void kernel_launch(void* const* d_in, const int* in_sizes, int n_in,
                              void* d_out, int out_size) {
    const float* x       = (const float*)d_in[0];
    const int*   qweight = (const int*)d_in[1];
    const float* scales  = (const float*)d_in[2];
    const int*   qzeros  = (const int*)d_in[3];
    float*       out     = (float*)d_out;

    const int M = in_sizes[0] / KDIM;            // 4096

    cvt_xq<<<(M / 16) * NK16 / 8, 256>>>(x);     // 8192 blocks
    dequant_w<<<dim3(KW / 32, 32), 256>>>(qweight, scales, qzeros);

    cudaFuncSetAttribute(w4_hgemm, cudaFuncAttributeMaxDynamicSharedMemorySize, SMEM_TOTAL);
    dim3 grid(M / BM, ODIM / BN);                // (32, 86) — bm fast
    w4_hgemm<<<grid, 128, SMEM_TOTAL>>>(out);
}

// round 11
// speedup vs baseline: 1.2561x; 1.2561x over previous
#include <cuda_runtime.h>
#include <cuda_fp16.h>
#include <cstdint>

#define KDIM 4096
#define ODIM 11008
#define KW   1376            // ODIM/8
#define BM 128
#define BN 128
#define NSTG 64              // KDIM/64
#define NK16 256             // KDIM/16

#define STG 16384            // B only: 128 rows x 128B
#define SMEM_TOTAL 49152     // 3 stages

__device__ uint4  g_xq[(size_t)256 * 256 * 32];   // A fragment-direct blocked layout
__device__ __half g_w16[(size_t)11008 * 4096];    // dequant weights fp16, [O][K]

// ---- pre-kernel 1: x fp32 -> fp16 fragment-direct layout ----
// tile (m16,k16): lane L holds 16B = {a0,a1,a2,a3}:
// a0=(m16*16+r, k16*16+c2), a1=(+8 row), a2=(row, k+8), a3=(row+8, k+8)
__global__ __launch_bounds__(256)
void cvt_xq(const float* __restrict__ x) {
    const int w    = threadIdx.x >> 5;
    const int lane = threadIdx.x & 31;
    const int ti   = blockIdx.x * 8 + w;        // 0..65535
    const int m16  = ti >> 8;
    const int k16  = ti & 255;
    const int r  = lane >> 2;
    const int c2 = (lane & 3) * 2;
    const size_t row0 = (size_t)(m16 * 16 + r) * KDIM;
    const size_t row1 = row0 + 8 * KDIM;
    const int k0 = k16 * 16 + c2;
    float2 v00 = *(const float2*)(x + row0 + k0);
    float2 v10 = *(const float2*)(x + row1 + k0);
    float2 v01 = *(const float2*)(x + row0 + k0 + 8);
    float2 v11 = *(const float2*)(x + row1 + k0 + 8);
    __half2 h0 = __floats2half2_rn(v00.x, v00.y);
    __half2 h1 = __floats2half2_rn(v10.x, v10.y);
    __half2 h2 = __floats2half2_rn(v01.x, v01.y);
    __half2 h3 = __floats2half2_rn(v11.x, v11.y);
    g_xq[(size_t)ti * 32 + lane] =
        make_uint4(*(unsigned*)&h0, *(unsigned*)&h1, *(unsigned*)&h2, *(unsigned*)&h3);
}

// ------- pre-kernel 2: dequantize weights to fp16 [O][K] (unchanged) -------
__global__ __launch_bounds__(256)
void dequant_w(const int* __restrict__ qweight, const float* __restrict__ scales,
               const int* __restrict__ qzeros) {
    const int w  = blockIdx.x * 32 + (threadIdx.x & 31);
    const int kb = blockIdx.y * 8  + (threadIdx.x >> 5);
    const int g  = kb >> 3;

    int qw[16];
    #pragma unroll
    for (int i = 0; i < 16; i++)
        qw[i] = qweight[(size_t)(kb * 16 + i) * KW + w];
    const int zw = qzeros[(size_t)g * KW + w];
    const float4 s0 = *(const float4*)(scales + (size_t)g * ODIM + w * 8);
    const float4 s1 = *(const float4*)(scales + (size_t)g * ODIM + w * 8 + 4);
    const float sv[8] = {s0.x, s0.y, s0.z, s0.w, s1.x, s1.y, s1.z, s1.w};

    #pragma unroll
    for (int j = 0; j < 8; j++) {
        const int z = (zw >> (4 * j)) & 15;
        const float s = sv[j];
        unsigned u[8];
        #pragma unroll
        for (int p = 0; p < 8; p++) {
            float f0 = (float)(((qw[2 * p]     >> (4 * j)) & 15) - z) * s;
            float f1 = (float)(((qw[2 * p + 1] >> (4 * j)) & 15) - z) * s;
            __half2 h = __floats2half2_rn(f0, f1);
            u[p] = *(unsigned*)&h;
        }
        __half* dst = g_w16 + (size_t)(w * 8 + j) * KDIM + kb * 16;
        *(uint4*)dst       = make_uint4(u[0], u[1], u[2], u[3]);
        *(uint4*)(dst + 8) = make_uint4(u[4], u[5], u[6], u[7]);
    }
}

// ---------------- helpers ----------------
#define CP16(dst, src) \
    asm volatile("cp.async.cg.shared.global [%0], [%1], 16;" :: "r"(dst), "l"(src))

static __device__ __forceinline__ void ldsm_x4(unsigned* r, unsigned addr) {
    asm volatile("ldmatrix.sync.aligned.m8n8.x4.shared.b16 {%0,%1,%2,%3}, [%4];"
                 : "=r"(r[0]), "=r"(r[1]), "=r"(r[2]), "=r"(r[3]) : "r"(addr));
}
static __device__ __forceinline__ void mma_f16(float* c, const unsigned* a,
                                               const unsigned* b) {
    asm volatile(
        "mma.sync.aligned.m16n8k16.row.col.f32.f16.f16.f32 "
        "{%0,%1,%2,%3}, {%4,%5,%6,%7}, {%8,%9}, {%0,%1,%2,%3};"
        : "+f"(c[0]), "+f"(c[1]), "+f"(c[2]), "+f"(c[3])
        : "r"(a[0]), "r"(a[1]), "r"(a[2]), "r"(a[3]), "r"(b[0]), "r"(b[1]));
}

// -- main GEMM: 256 thr, 8 warps 2x4 (warp 64x32), A direct LDG, B smem ring --
__global__ __launch_bounds__(256, 2)
void w4_hgemm(float* __restrict__ out) {
    extern __shared__ char smem[];
    const int tid  = threadIdx.x;
    const int lane = tid & 31;
    const int wid  = tid >> 5;
    const int wm   = wid >> 2;                 // 0..1  (64 rows)
    const int wn   = wid & 3;                  // 0..3  (32 cols)
    const int bm0  = blockIdx.x * BM;          // bm fast
    const int bn0  = blockIdx.y * BN;

    const char*  gb  = (const char*)(g_w16 + (size_t)bn0 * KDIM);
    const uint4* gaq = g_xq + ((size_t)(bm0 / 16 + wm * 4) * NK16) * 32 + lane;

    float acc[4][4][4];
    #pragma unroll
    for (int i = 0; i < 4; i++)
        #pragma unroll
        for (int j = 0; j < 4; j++)
            #pragma unroll
            for (int q = 0; q < 4; q++) acc[i][j][q] = 0.0f;

    auto issueB = [&](int t) {
        char* s = smem + (t % 3) * STG;
        #pragma unroll
        for (int i = 0; i < 4; i++) {            // B: 1024 16B chunks
            const int idx = tid + 256 * i;
            const int n  = idx >> 3;             // 0..127
            const int ch = idx & 7;
            unsigned d = (unsigned)__cvta_generic_to_shared(
                s + n * 128 + ((ch ^ (n & 7)) * 16));
            CP16(d, gb + (size_t)n * 8192 + (size_t)t * 128 + ch * 16);
        }
        asm volatile("cp.async.commit_group;");
    };

    issueB(0);
    issueB(1);

    const int bg = lane >> 3;                    // 0..3 B matrix group

    // A frag load: (mt, k16) -> uint4 (wrap k16 to stay in-bounds; wrapped unused)
    auto ldA = [&](int mt, int k16) {
        return gaq[((size_t)mt * NK16 + (k16 & 255)) * 32];
    };

    uint4 abuf[2][4];
    #pragma unroll
    for (int mt = 0; mt < 4; mt++) abuf[0][mt] = ldA(mt, 0);

    #pragma unroll 1
    for (int t = 0; t < NSTG; t++) {
        if (t + 1 < NSTG) asm volatile("cp.async.wait_group 1;");
        else              asm volatile("cp.async.wait_group 0;");
        __syncthreads();
        if (t + 2 < NSTG) issueB(t + 2);

        const char* Bs = smem + (t % 3) * STG;

        #pragma unroll
        for (int ks = 0; ks < 4; ks++) {         // ping-pong A buffers, no MOVs
            const int cur = ks & 1;
            const int nxt = cur ^ 1;
            #pragma unroll
            for (int mt = 0; mt < 4; mt++)
                abuf[nxt][mt] = ldA(mt, t * 4 + ks + 1);   // 1-ks lookahead
            unsigned b[4][2];
            #pragma unroll
            for (int p = 0; p < 2; p++) {        // each x4 fills frags 2p, 2p+1
                const int n  = wn * 32 + p * 16 + ((bg >> 1) << 3) + (lane & 7);
                const int ch = 2 * ks + (bg & 1);
                ldsm_x4(&b[2 * p][0], (unsigned)__cvta_generic_to_shared(
                    Bs + n * 128 + ((ch ^ (n & 7)) * 16)));
            }
            #pragma unroll
            for (int mt = 0; mt < 4; mt++)
                #pragma unroll
                for (int nt = 0; nt < 4; nt++)
                    mma_f16(acc[mt][nt], (const unsigned*)&abuf[cur][mt], b[nt]);
        }
    }

    // ---- epilogue: streaming stores (keep A/B resident in L2) ----
    const int r = lane >> 2;
    const int c = lane & 3;
    #pragma unroll
    for (int mt = 0; mt < 4; mt++) {
        #pragma unroll
        for (int nt = 0; nt < 4; nt++) {
            const int row = bm0 + wm * 64 + mt * 16 + r;
            const int col = bn0 + wn * 32 + nt * 8 + c * 2;
            float* p = out + (size_t)row * ODIM + col;
            __stcs((float2*)p, make_float2(acc[mt][nt][0], acc[mt][nt][1]));
            __stcs((float2*)(p + (size_t)8 * ODIM),
                   make_float2(acc[mt][nt][2], acc[mt][nt][3]));
        }
    }
}

extern "C" void kernel_launch(void* const* d_in, const int* in_sizes, int n_in,
                              void* d_out, int out_size) {
    const float* x       = (const float*)d_in[0];
    const int*   qweight = (const int*)d_in[1];
    const float* scales  = (const float*)d_in[2];
    const int*   qzeros  = (const int*)d_in[3];
    float*       out     = (float*)d_out;

    const int M = in_sizes[0] / KDIM;            // 4096

    cvt_xq<<<(M / 16) * NK16 / 8, 256>>>(x);     // 8192 blocks
    dequant_w<<<dim3(KW / 32, 32), 256>>>(qweight, scales, qzeros);

    cudaFuncSetAttribute(w4_hgemm, cudaFuncAttributeMaxDynamicSharedMemorySize, SMEM_TOTAL);
    dim3 grid(M / BM, ODIM / BN);                // (32, 86) — bm fast
    w4_hgemm<<<grid, 256, SMEM_TOTAL>>>(out);
}

// round 13
// speedup vs baseline: 1.3121x; 1.0446x over previous
#include <cuda_runtime.h>
#include <cuda.h>
#include <cuda_fp16.h>
#include <cstdint>

#define KDIM 4096
#define ODIM 11008
#define KW   1376            // ODIM/8
#define BM 128
#define BN 128
#define NSTG 64              // KDIM/64

#define ASZ 16384            // 128 rows x 128B (64 f16)
#define STG 32768            // A + B per stage
#define MBAR_OFF 98304       // after 3 stages
#define SMEM_TOTAL 98432     // 3 stages + mbarriers/pad

__device__ __half g_x16[(size_t)4096 * 4096];     // x as fp16, [M][K]
__device__ __half g_w16[(size_t)11008 * 4096];    // dequant weights fp16, [O][K]

// ---------------- pre-kernel 1: x fp32 -> fp16 ----------------
__global__ __launch_bounds__(256)
void cvt_x(const float* __restrict__ x) {
    size_t i = ((size_t)blockIdx.x * 256 + threadIdx.x) * 4;
    float4 v = *(const float4*)(x + i);
    __half2 h0 = __floats2half2_rn(v.x, v.y);
    __half2 h1 = __floats2half2_rn(v.z, v.w);
    uint2 u;
    u.x = *(unsigned*)&h0;
    u.y = *(unsigned*)&h1;
    *(uint2*)(g_x16 + i) = u;
}

// ------- pre-kernel 2: dequantize weights to fp16 [O][K] -------
__global__ __launch_bounds__(256)
void dequant_w(const int* __restrict__ qweight, const float* __restrict__ scales,
               const int* __restrict__ qzeros) {
    const int w  = blockIdx.x * 32 + (threadIdx.x & 31);
    const int kb = blockIdx.y * 8  + (threadIdx.x >> 5);
    const int g  = kb >> 3;

    int qw[16];
    #pragma unroll
    for (int i = 0; i < 16; i++)
        qw[i] = qweight[(size_t)(kb * 16 + i) * KW + w];
    const int zw = qzeros[(size_t)g * KW + w];
    const float4 s0 = *(const float4*)(scales + (size_t)g * ODIM + w * 8);
    const float4 s1 = *(const float4*)(scales + (size_t)g * ODIM + w * 8 + 4);
    const float sv[8] = {s0.x, s0.y, s0.z, s0.w, s1.x, s1.y, s1.z, s1.w};

    #pragma unroll
    for (int j = 0; j < 8; j++) {
        const int z = (zw >> (4 * j)) & 15;
        const float s = sv[j];
        unsigned u[8];
        #pragma unroll
        for (int p = 0; p < 8; p++) {
            float f0 = (float)(((qw[2 * p]     >> (4 * j)) & 15) - z) * s;
            float f1 = (float)(((qw[2 * p + 1] >> (4 * j)) & 15) - z) * s;
            __half2 h = __floats2half2_rn(f0, f1);
            u[p] = *(unsigned*)&h;
        }
        __half* dst = g_w16 + (size_t)(w * 8 + j) * KDIM + kb * 16;
        *(uint4*)dst       = make_uint4(u[0], u[1], u[2], u[3]);
        *(uint4*)(dst + 8) = make_uint4(u[4], u[5], u[6], u[7]);
    }
}

// ---------------- helpers ----------------
static __device__ __forceinline__ void ldsm_x4(unsigned* r, unsigned addr) {
    asm volatile("ldmatrix.sync.aligned.m8n8.x4.shared.b16 {%0,%1,%2,%3}, [%4];"
                 : "=r"(r[0]), "=r"(r[1]), "=r"(r[2]), "=r"(r[3]) : "r"(addr));
}
static __device__ __forceinline__ void mma_f16(float* c, const unsigned* a,
                                               const unsigned* b) {
    asm volatile(
        "mma.sync.aligned.m16n8k16.row.col.f32.f16.f16.f32 "
        "{%0,%1,%2,%3}, {%4,%5,%6,%7}, {%8,%9}, {%0,%1,%2,%3};"
        : "+f"(c[0]), "+f"(c[1]), "+f"(c[2]), "+f"(c[3])
        : "r"(a[0]), "r"(a[1]), "r"(a[2]), "r"(a[3]), "r"(b[0]), "r"(b[1]));
}
static __device__ __forceinline__ void mbar_wait(unsigned a, unsigned parity) {
    asm volatile(
        "{\n\t.reg .pred P;\n\t"
        "WL%=:\n\t"
        "mbarrier.try_wait.parity.acquire.cta.shared::cta.b64 P, [%0], %1, 0x989680;\n\t"
        "@P bra.uni WD%=;\n\t"
        "bra.uni WL%=;\n\t"
        "WD%=:\n\t}"
        :: "r"(a), "r"(parity) : "memory");
}

// -- main GEMM: R6 config (128x128, warp 64x32, 2 CTAs/SM), TMA-fed --
__global__ __launch_bounds__(256, 2)
void w4_hgemm(const __grid_constant__ CUtensorMap tma_a,
              const __grid_constant__ CUtensorMap tma_b,
              float* __restrict__ out) {
    extern __shared__ __align__(1024) char smem[];
    unsigned sbase;
    asm("{ .reg .u64 t; cvta.to.shared.u64 t, %1; cvt.u32.u64 %0, t; }"
        : "=r"(sbase) : "l"(smem));
    const int tid  = threadIdx.x;
    const int lane = tid & 31;
    const int wid  = tid >> 5;
    const int wm   = wid >> 2;                 // 0..1  (64 rows)
    const int wn   = wid & 3;                  // 0..3  (32 cols)
    const int bm0  = blockIdx.x * BM;          // bm fast
    const int bn0  = blockIdx.y * BN;

    if (tid == 0) {
        #pragma unroll
        for (int s = 0; s < 3; s++)
            asm volatile("mbarrier.init.shared.b64 [%0], 1;"
                         :: "r"(sbase + MBAR_OFF + s * 8) : "memory");
    }
    __syncthreads();

    auto issue = [&](int t) {                  // one thread: expect_tx + 2 TMA
        const int s = t % 3;
        const unsigned mb = sbase + MBAR_OFF + s * 8;
        asm volatile("mbarrier.arrive.expect_tx.shared.b64 _, [%0], %1;"
                     :: "r"(mb), "r"((unsigned)STG) : "memory");
        asm volatile(
            "cp.async.bulk.tensor.2d.shared::cta.global.tile.mbarrier::complete_tx::bytes "
            "[%0], [%1, {%2, %3}], [%4];"
            :: "r"(sbase + s * STG), "l"(&tma_a), "r"(t * 64), "r"(bm0), "r"(mb)
            : "memory");
        asm volatile(
            "cp.async.bulk.tensor.2d.shared::cta.global.tile.mbarrier::complete_tx::bytes "
            "[%0], [%1, {%2, %3}], [%4];"
            :: "r"(sbase + s * STG + ASZ), "l"(&tma_b), "r"(t * 64), "r"(bn0), "r"(mb)
            : "memory");
    };
    if (tid == 0) { issue(0); issue(1); }

    float acc[4][4][4];
    #pragma unroll
    for (int i = 0; i < 4; i++)
        #pragma unroll
        for (int j = 0; j < 4; j++)
            #pragma unroll
            for (int q = 0; q < 4; q++) acc[i][j][q] = 0.0f;

    const int arow = lane & 15;
    const int asel = lane >> 4;
    const int bg   = lane >> 3;                  // 0..3
    const int r = lane >> 2;
    const int c = lane & 3;

    #pragma unroll 1
    for (int t = 0; t < NSTG; t++) {
        const int s = t % 3;
        mbar_wait(sbase + MBAR_OFF + s * 8, (unsigned)((t / 3) & 1));
        __syncthreads();                         // all readers of buffer (t+2)%3 done
        if (t + 2 < NSTG && tid == 0) issue(t + 2);

        const unsigned As = sbase + s * STG;
        const unsigned Bs = As + ASZ;

        #pragma unroll
        for (int ks = 0; ks < 4; ks++) {         // 4 x k16 steps = 64 k
            unsigned a[4][4], b[4][2];
            #pragma unroll
            for (int mt = 0; mt < 4; mt++) {
                const int row = wm * 64 + mt * 16 + arow;
                const int ch  = 2 * ks + asel;
                ldsm_x4(a[mt], As + row * 128 + ((ch ^ (row & 7)) * 16));
            }
            #pragma unroll
            for (int p = 0; p < 2; p++) {        // each x4 fills frags 2p, 2p+1
                const int n  = wn * 32 + p * 16 + ((bg >> 1) << 3) + (lane & 7);
                const int ch = 2 * ks + (bg & 1);
                ldsm_x4(&b[2 * p][0], Bs + n * 128 + ((ch ^ (n & 7)) * 16));
            }
            #pragma unroll
            for (int mt = 0; mt < 4; mt++)
                #pragma unroll
                for (int nt = 0; nt < 4; nt++)
                    mma_f16(acc[mt][nt], a[mt], b[nt]);
        }
    }

    // ---- epilogue: streaming stores (keep A/B resident in L2) ----
    #pragma unroll
    for (int mt = 0; mt < 4; mt++) {
        #pragma unroll
        for (int nt = 0; nt < 4; nt++) {
            const int row = bm0 + wm * 64 + mt * 16 + r;
            const int col = bn0 + wn * 32 + nt * 8 + c * 2;
            float* p = out + (size_t)row * ODIM + col;
            __stcs((float2*)p, make_float2(acc[mt][nt][0], acc[mt][nt][1]));
            __stcs((float2*)(p + (size_t)8 * ODIM),
                   make_float2(acc[mt][nt][2], acc[mt][nt][3]));
        }
    }
}

// Driver entry point fetched through cudart (no -lcuda needed at link time)
typedef CUresult (*PFN_encodeTiled)(
    CUtensorMap*, CUtensorMapDataType, cuuint32_t, void*,
    const cuuint64_t*, const cuuint64_t*, const cuuint32_t*, const cuuint32_t*,
    CUtensorMapInterleave, CUtensorMapSwizzle, CUtensorMapL2promotion,
    CUtensorMapFloatOOBfill);

extern "C" void kernel_launch(void* const* d_in, const int* in_sizes, int n_in,
                              void* d_out, int out_size) {
    const float* x       = (const float*)d_in[0];
    const int*   qweight = (const int*)d_in[1];
    const float* scales  = (const float*)d_in[2];
    const int*   qzeros  = (const int*)d_in[3];
    float*       out     = (float*)d_out;

    const int M = in_sizes[0] / KDIM;            // 4096

    cvt_x<<<(M * KDIM) / (256 * 4), 256>>>(x);
    dequant_w<<<dim3(KW / 32, 32), 256>>>(qweight, scales, qzeros);

    static CUtensorMap tma_a, tma_b;
    static bool built = false;
    if (!built) {
        PFN_encodeTiled encode = nullptr;
        cudaDriverEntryPointQueryResult qr;
#if CUDART_VERSION >= 12050
        cudaGetDriverEntryPointByVersion("cuTensorMapEncodeTiled",
                                         (void**)&encode, 12000,
                                         cudaEnableDefault, &qr);
#else
        cudaGetDriverEntryPoint("cuTensorMapEncodeTiled",
                                (void**)&encode, cudaEnableDefault, &qr);
#endif
        void *pa = nullptr, *pb = nullptr;
        cudaGetSymbolAddress(&pa, g_x16);
        cudaGetSymbolAddress(&pb, g_w16);
        cuuint64_t dims_a[2] = {(cuuint64_t)KDIM, (cuuint64_t)M};
        cuuint64_t dims_b[2] = {(cuuint64_t)KDIM, (cuuint64_t)ODIM};
        cuuint64_t strides[1] = {(cuuint64_t)KDIM * 2};
        cuuint32_t box[2] = {64, 128};
        cuuint32_t es[2] = {1, 1};
        encode(&tma_a, CU_TENSOR_MAP_DATA_TYPE_UINT16, 2, pa,
               dims_a, strides, box, es,
               CU_TENSOR_MAP_INTERLEAVE_NONE, CU_TENSOR_MAP_SWIZZLE_128B,
               CU_TENSOR_MAP_L2_PROMOTION_L2_128B, CU_TENSOR_MAP_FLOAT_OOB_FILL_NONE);
        encode(&tma_b, CU_TENSOR_MAP_DATA_TYPE_UINT16, 2, pb,
               dims_b, strides, box, es,
               CU_TENSOR_MAP_INTERLEAVE_NONE, CU_TENSOR_MAP_SWIZZLE_128B,
               CU_TENSOR_MAP_L2_PROMOTION_L2_128B, CU_TENSOR_MAP_FLOAT_OOB_FILL_NONE);
        built = true;
    }

    cudaFuncSetAttribute(w4_hgemm, cudaFuncAttributeMaxDynamicSharedMemorySize,
                         SMEM_TOTAL);
    dim3 grid(M / BM, ODIM / BN);                // (32, 86) — bm fast
    w4_hgemm<<<grid, 256, SMEM_TOTAL>>>(tma_a, tma_b, out);
}

// round 14
// speedup vs baseline: 1.4155x; 1.0788x over previous
#include <cuda_runtime.h>
#include <cuda.h>
#include <cuda_fp16.h>
#include <cstdint>

#define KDIM 4096
#define ODIM 11008
#define KW   1376            // ODIM/8
#define BM 128
#define BN 128
#define NSTG 64              // KDIM/64

#define ASZ 16384            // 128 rows x 128B (64 f16)
#define STG 32768            // A + B per stage
#define MBAR_OFF 98304       // after 3 stages: full[3] then empty[3]
#define SMEM_TOTAL 98432

__device__ __half g_x16[(size_t)4096 * 4096];     // x as fp16, [M][K]
__device__ __half g_w16[(size_t)11008 * 4096];    // dequant weights fp16, [O][K]

// ---------------- pre-kernel 1: x fp32 -> fp16 ----------------
__global__ __launch_bounds__(256)
void cvt_x(const float* __restrict__ x) {
    size_t i = ((size_t)blockIdx.x * 256 + threadIdx.x) * 4;
    float4 v = *(const float4*)(x + i);
    __half2 h0 = __floats2half2_rn(v.x, v.y);
    __half2 h1 = __floats2half2_rn(v.z, v.w);
    uint2 u;
    u.x = *(unsigned*)&h0;
    u.y = *(unsigned*)&h1;
    *(uint2*)(g_x16 + i) = u;
}

// ------- pre-kernel 2: dequantize weights to fp16 [O][K] -------
__global__ __launch_bounds__(256)
void dequant_w(const int* __restrict__ qweight, const float* __restrict__ scales,
               const int* __restrict__ qzeros) {
    const int w  = blockIdx.x * 32 + (threadIdx.x & 31);
    const int kb = blockIdx.y * 8  + (threadIdx.x >> 5);
    const int g  = kb >> 3;

    int qw[16];
    #pragma unroll
    for (int i = 0; i < 16; i++)
        qw[i] = qweight[(size_t)(kb * 16 + i) * KW + w];
    const int zw = qzeros[(size_t)g * KW + w];
    const float4 s0 = *(const float4*)(scales + (size_t)g * ODIM + w * 8);
    const float4 s1 = *(const float4*)(scales + (size_t)g * ODIM + w * 8 + 4);
    const float sv[8] = {s0.x, s0.y, s0.z, s0.w, s1.x, s1.y, s1.z, s1.w};

    #pragma unroll
    for (int j = 0; j < 8; j++) {
        const int z = (zw >> (4 * j)) & 15;
        const float s = sv[j];
        unsigned u[8];
        #pragma unroll
        for (int p = 0; p < 8; p++) {
            float f0 = (float)(((qw[2 * p]     >> (4 * j)) & 15) - z) * s;
            float f1 = (float)(((qw[2 * p + 1] >> (4 * j)) & 15) - z) * s;
            __half2 h = __floats2half2_rn(f0, f1);
            u[p] = *(unsigned*)&h;
        }
        __half* dst = g_w16 + (size_t)(w * 8 + j) * KDIM + kb * 16;
        *(uint4*)dst       = make_uint4(u[0], u[1], u[2], u[3]);
        *(uint4*)(dst + 8) = make_uint4(u[4], u[5], u[6], u[7]);
    }
}

// ---------------- helpers ----------------
static __device__ __forceinline__ void ldsm_x4(unsigned* r, unsigned addr) {
    asm volatile("ldmatrix.sync.aligned.m8n8.x4.shared.b16 {%0,%1,%2,%3}, [%4];"
                 : "=r"(r[0]), "=r"(r[1]), "=r"(r[2]), "=r"(r[3]) : "r"(addr));
}
static __device__ __forceinline__ void mma_f16(float* c, const unsigned* a,
                                               const unsigned* b) {
    asm volatile(
        "mma.sync.aligned.m16n8k16.row.col.f32.f16.f16.f32 "
        "{%0,%1,%2,%3}, {%4,%5,%6,%7}, {%8,%9}, {%0,%1,%2,%3};"
        : "+f"(c[0]), "+f"(c[1]), "+f"(c[2]), "+f"(c[3])
        : "r"(a[0]), "r"(a[1]), "r"(a[2]), "r"(a[3]), "r"(b[0]), "r"(b[1]));
}
static __device__ __forceinline__ void mbar_wait(unsigned a, unsigned parity) {
    asm volatile(
        "{\n\t.reg .pred P;\n\t"
        "WL%=:\n\t"
        "mbarrier.try_wait.parity.acquire.cta.shared::cta.b64 P, [%0], %1, 0x989680;\n\t"
        "@P bra.uni WD%=;\n\t"
        "bra.uni WL%=;\n\t"
        "WD%=:\n\t}"
        :: "r"(a), "r"(parity) : "memory");
}
static __device__ __forceinline__ void mbar_arrive(unsigned a) {
    asm volatile("mbarrier.arrive.release.cta.shared::cta.b64 _, [%0];"
                 :: "r"(a) : "memory");
}

// -- main GEMM: 128x128, warp 64x32, 2 CTAs/SM, TMA-fed, barrier-free mainloop --
__global__ __launch_bounds__(256, 2)
void w4_hgemm(const __grid_constant__ CUtensorMap tma_a,
              const __grid_constant__ CUtensorMap tma_b,
              float* __restrict__ out) {
    extern __shared__ __align__(1024) char smem[];
    unsigned sbase;
    asm("{ .reg .u64 t; cvta.to.shared.u64 t, %1; cvt.u32.u64 %0, t; }"
        : "=r"(sbase) : "l"(smem));
    const int tid  = threadIdx.x;
    const int lane = tid & 31;
    const int wid  = tid >> 5;
    const int wm   = wid >> 2;                 // 0..1  (64 rows)
    const int wn   = wid & 3;                  // 0..3  (32 cols)
    const int bm0  = blockIdx.x * BM;          // bm fast
    const int bn0  = blockIdx.y * BN;

    const unsigned FULL  = sbase + MBAR_OFF;        // 3 x 8B, count 1
    const unsigned EMPTY = sbase + MBAR_OFF + 24;   // 3 x 8B, count 8 (per-warp)

    if (tid == 0) {
        #pragma unroll
        for (int s = 0; s < 3; s++) {
            asm volatile("mbarrier.init.shared.b64 [%0], 1;"
                         :: "r"(FULL + s * 8) : "memory");
            asm volatile("mbarrier.init.shared.b64 [%0], 8;"
                         :: "r"(EMPTY + s * 8) : "memory");
        }
    }
    __syncthreads();

    auto issue = [&](int t) {                  // one thread: expect_tx + 2 TMA
        const int s = t % 3;
        const unsigned mb = FULL + s * 8;
        asm volatile("mbarrier.arrive.expect_tx.shared.b64 _, [%0], %1;"
                     :: "r"(mb), "r"((unsigned)STG) : "memory");
        asm volatile(
            "cp.async.bulk.tensor.2d.shared::cta.global.tile.mbarrier::complete_tx::bytes "
            "[%0], [%1, {%2, %3}], [%4];"
            :: "r"(sbase + s * STG), "l"(&tma_a), "r"(t * 64), "r"(bm0), "r"(mb)
            : "memory");
        asm volatile(
            "cp.async.bulk.tensor.2d.shared::cta.global.tile.mbarrier::complete_tx::bytes "
            "[%0], [%1, {%2, %3}], [%4];"
            :: "r"(sbase + s * STG + ASZ), "l"(&tma_b), "r"(t * 64), "r"(bn0), "r"(mb)
            : "memory");
    };
    if (tid == 0) { issue(0); issue(1); issue(2); }

    float acc[4][4][4];
    #pragma unroll
    for (int i = 0; i < 4; i++)
        #pragma unroll
        for (int j = 0; j < 4; j++)
            #pragma unroll
            for (int q = 0; q < 4; q++) acc[i][j][q] = 0.0f;

    const int arow = lane & 15;
    const int asel = lane >> 4;
    const int bg   = lane >> 3;                  // 0..3
    const int r = lane >> 2;
    const int c = lane & 3;

    #pragma unroll 1
    for (int t = 0; t < NSTG; t++) {
        const int s = t % 3;
        const unsigned par = (unsigned)((t / 3) & 1);
        mbar_wait(FULL + s * 8, par);            // own data dependency only

        const unsigned As = sbase + s * STG;
        const unsigned Bs = As + ASZ;

        #pragma unroll
        for (int ks = 0; ks < 4; ks++) {         // 4 x k16 steps = 64 k
            unsigned a[4][4], b[4][2];
            #pragma unroll
            for (int mt = 0; mt < 4; mt++) {
                const int row = wm * 64 + mt * 16 + arow;
                const int ch  = 2 * ks + asel;
                ldsm_x4(a[mt], As + row * 128 + ((ch ^ (row & 7)) * 16));
            }
            #pragma unroll
            for (int p = 0; p < 2; p++) {        // each x4 fills frags 2p, 2p+1
                const int n  = wn * 32 + p * 16 + ((bg >> 1) << 3) + (lane & 7);
                const int ch = 2 * ks + (bg & 1);
                ldsm_x4(&b[2 * p][0], Bs + n * 128 + ((ch ^ (n & 7)) * 16));
            }
            #pragma unroll
            for (int mt = 0; mt < 4; mt++)
                #pragma unroll
                for (int nt = 0; nt < 4; nt++)
                    mma_f16(acc[mt][nt], a[mt], b[nt]);
        }

        __syncwarp();
        if (lane == 0) mbar_arrive(EMPTY + s * 8);   // warp done reading buffer s

        if (tid == 0 && t + 3 < NSTG) {
            mbar_wait(EMPTY + s * 8, par);           // all 8 warps released s
            issue(t + 3);                            // reuse buffer s
        }
    }

    // ---- epilogue: streaming stores (keep A/B resident in L2) ----
    #pragma unroll
    for (int mt = 0; mt < 4; mt++) {
        #pragma unroll
        for (int nt = 0; nt < 4; nt++) {
            const int row = bm0 + wm * 64 + mt * 16 + r;
            const int col = bn0 + wn * 32 + nt * 8 + c * 2;
            float* p = out + (size_t)row * ODIM + col;
            __stcs((float2*)p, make_float2(acc[mt][nt][0], acc[mt][nt][1]));
            __stcs((float2*)(p + (size_t)8 * ODIM),
                   make_float2(acc[mt][nt][2], acc[mt][nt][3]));
        }
    }
}

// Driver entry point fetched through cudart (no -lcuda needed at link time)
typedef CUresult (*PFN_encodeTiled)(
    CUtensorMap*, CUtensorMapDataType, cuuint32_t, void*,
    const cuuint64_t*, const cuuint64_t*, const cuuint32_t*, const cuuint32_t*,
    CUtensorMapInterleave, CUtensorMapSwizzle, CUtensorMapL2promotion,
    CUtensorMapFloatOOBfill);

extern "C" void kernel_launch(void* const* d_in, const int* in_sizes, int n_in,
                              void* d_out, int out_size) {
    const float* x       = (const float*)d_in[0];
    const int*   qweight = (const int*)d_in[1];
    const float* scales  = (const float*)d_in[2];
    const int*   qzeros  = (const int*)d_in[3];
    float*       out     = (float*)d_out;

    const int M = in_sizes[0] / KDIM;            // 4096

    cvt_x<<<(M * KDIM) / (256 * 4), 256>>>(x);
    dequant_w<<<dim3(KW / 32, 32), 256>>>(qweight, scales, qzeros);

    static CUtensorMap tma_a, tma_b;
    static bool built = false;
    if (!built) {
        PFN_encodeTiled encode = nullptr;
        cudaDriverEntryPointQueryResult qr;
#if CUDART_VERSION >= 12050
        cudaGetDriverEntryPointByVersion("cuTensorMapEncodeTiled",
                                         (void**)&encode, 12000,
                                         cudaEnableDefault, &qr);
#else
        cudaGetDriverEntryPoint("cuTensorMapEncodeTiled",
                                (void**)&encode, cudaEnableDefault, &qr);
#endif
        void *pa = nullptr, *pb = nullptr;
        cudaGetSymbolAddress(&pa, g_x16);
        cudaGetSymbolAddress(&pb, g_w16);
        cuuint64_t dims_a[2] = {(cuuint64_t)KDIM, (cuuint64_t)M};
        cuuint64_t dims_b[2] = {(cuuint64_t)KDIM, (cuuint64_t)ODIM};
        cuuint64_t strides[1] = {(cuuint64_t)KDIM * 2};
        cuuint32_t box[2] = {64, 128};
        cuuint32_t es[2] = {1, 1};
        encode(&tma_a, CU_TENSOR_MAP_DATA_TYPE_UINT16, 2, pa,
               dims_a, strides, box, es,
               CU_TENSOR_MAP_INTERLEAVE_NONE, CU_TENSOR_MAP_SWIZZLE_128B,
               CU_TENSOR_MAP_L2_PROMOTION_L2_128B, CU_TENSOR_MAP_FLOAT_OOB_FILL_NONE);
        encode(&tma_b, CU_TENSOR_MAP_DATA_TYPE_UINT16, 2, pb,
               dims_b, strides, box, es,
               CU_TENSOR_MAP_INTERLEAVE_NONE, CU_TENSOR_MAP_SWIZZLE_128B,
               CU_TENSOR_MAP_L2_PROMOTION_L2_128B, CU_TENSOR_MAP_FLOAT_OOB_FILL_NONE);
        built = true;
    }

    cudaFuncSetAttribute(w4_hgemm, cudaFuncAttributeMaxDynamicSharedMemorySize,
                         SMEM_TOTAL);
    dim3 grid(M / BM, ODIM / BN);                // (32, 86) — bm fast
    w4_hgemm<<<grid, 256, SMEM_TOTAL>>>(tma_a, tma_b, out);
}

// round 15
// speedup vs baseline: 1.4771x; 1.0436x over previous
#include <cuda_runtime.h>
#include <cuda.h>
#include <cuda_fp16.h>
#include <cstdint>

#define KDIM 4096
#define ODIM 11008
#define KW   1376            // ODIM/8
#define BM 128
#define BN 128
#define NSTG 64              // KDIM/64

#define ASZ 16384            // 128 rows x 128B (64 f16)
#define STG 32768            // A + B per stage
#define MBAR_OFF 98304       // after 3 stages: full[3] then empty[3]
#define SMEM_TOTAL 98432

__device__ __half g_x16[(size_t)4096 * 4096];     // x as fp16, [M][K]
__device__ __half g_w16[(size_t)11008 * 4096];    // dequant weights fp16, [O][K]

// ---------------- pre-kernel 1: x fp32 -> fp16 ----------------
__global__ __launch_bounds__(256)
void cvt_x(const float* __restrict__ x) {
    size_t i = ((size_t)blockIdx.x * 256 + threadIdx.x) * 4;
    float4 v = *(const float4*)(x + i);
    __half2 h0 = __floats2half2_rn(v.x, v.y);
    __half2 h1 = __floats2half2_rn(v.z, v.w);
    uint2 u;
    u.x = *(unsigned*)&h0;
    u.y = *(unsigned*)&h1;
    *(uint2*)(g_x16 + i) = u;
}

// ------- pre-kernel 2: dequantize weights to fp16 [O][K] -------
__global__ __launch_bounds__(256)
void dequant_w(const int* __restrict__ qweight, const float* __restrict__ scales,
               const int* __restrict__ qzeros) {
    const int w  = blockIdx.x * 32 + (threadIdx.x & 31);
    const int kb = blockIdx.y * 8  + (threadIdx.x >> 5);
    const int g  = kb >> 3;

    int qw[16];
    #pragma unroll
    for (int i = 0; i < 16; i++)
        qw[i] = qweight[(size_t)(kb * 16 + i) * KW + w];
    const int zw = qzeros[(size_t)g * KW + w];
    const float4 s0 = *(const float4*)(scales + (size_t)g * ODIM + w * 8);
    const float4 s1 = *(const float4*)(scales + (size_t)g * ODIM + w * 8 + 4);
    const float sv[8] = {s0.x, s0.y, s0.z, s0.w, s1.x, s1.y, s1.z, s1.w};

    #pragma unroll
    for (int j = 0; j < 8; j++) {
        const int z = (zw >> (4 * j)) & 15;
        const float s = sv[j];
        unsigned u[8];
        #pragma unroll
        for (int p = 0; p < 8; p++) {
            float f0 = (float)(((qw[2 * p]     >> (4 * j)) & 15) - z) * s;
            float f1 = (float)(((qw[2 * p + 1] >> (4 * j)) & 15) - z) * s;
            __half2 h = __floats2half2_rn(f0, f1);
            u[p] = *(unsigned*)&h;
        }
        __half* dst = g_w16 + (size_t)(w * 8 + j) * KDIM + kb * 16;
        *(uint4*)dst       = make_uint4(u[0], u[1], u[2], u[3]);
        *(uint4*)(dst + 8) = make_uint4(u[4], u[5], u[6], u[7]);
    }
}

// ---------------- helpers ----------------
static __device__ __forceinline__ void ldsm_x4(unsigned* r, unsigned addr) {
    asm volatile("ldmatrix.sync.aligned.m8n8.x4.shared.b16 {%0,%1,%2,%3}, [%4];"
                 : "=r"(r[0]), "=r"(r[1]), "=r"(r[2]), "=r"(r[3]) : "r"(addr));
}
static __device__ __forceinline__ void mma_f16(float* c, const unsigned* a,
                                               const unsigned* b) {
    asm volatile(
        "mma.sync.aligned.m16n8k16.row.col.f32.f16.f16.f32 "
        "{%0,%1,%2,%3}, {%4,%5,%6,%7}, {%8,%9}, {%0,%1,%2,%3};"
        : "+f"(c[0]), "+f"(c[1]), "+f"(c[2]), "+f"(c[3])
        : "r"(a[0]), "r"(a[1]), "r"(a[2]), "r"(a[3]), "r"(b[0]), "r"(b[1]));
}
static __device__ __forceinline__ void mbar_wait(unsigned a, unsigned parity) {
    asm volatile(
        "{\n\t.reg .pred P;\n\t"
        "WL%=:\n\t"
        "mbarrier.try_wait.parity.acquire.cta.shared::cta.b64 P, [%0], %1, 0x989680;\n\t"
        "@P bra.uni WD%=;\n\t"
        "bra.uni WL%=;\n\t"
        "WD%=:\n\t}"
        :: "r"(a), "r"(parity) : "memory");
}
static __device__ __forceinline__ void mbar_arrive(unsigned a) {
    asm volatile("mbarrier.arrive.release.cta.shared::cta.b64 _, [%0];"
                 :: "r"(a) : "memory");
}

// -- main GEMM: 128 thr, 4 warps 2x2 (warp 64x64), TMA-fed, mbarrier pipeline --
__global__ __launch_bounds__(128, 2)
void w4_hgemm(const __grid_constant__ CUtensorMap tma_a,
              const __grid_constant__ CUtensorMap tma_b,
              float* __restrict__ out) {
    extern __shared__ __align__(1024) char smem[];
    unsigned sbase;
    asm("{ .reg .u64 t; cvta.to.shared.u64 t, %1; cvt.u32.u64 %0, t; }"
        : "=r"(sbase) : "l"(smem));
    const int tid  = threadIdx.x;
    const int lane = tid & 31;
    const int wid  = tid >> 5;
    const int wm   = wid >> 1;                 // 0..1  (64 rows)
    const int wn   = wid & 1;                  // 0..1  (64 cols)
    const int bm0  = blockIdx.x * BM;          // bm fast
    const int bn0  = blockIdx.y * BN;

    const unsigned FULL  = sbase + MBAR_OFF;        // 3 x 8B, count 1
    const unsigned EMPTY = sbase + MBAR_OFF + 24;   // 3 x 8B, count 4 (per-warp)

    if (tid == 0) {
        #pragma unroll
        for (int s = 0; s < 3; s++) {
            asm volatile("mbarrier.init.shared.b64 [%0], 1;"
                         :: "r"(FULL + s * 8) : "memory");
            asm volatile("mbarrier.init.shared.b64 [%0], 4;"
                         :: "r"(EMPTY + s * 8) : "memory");
        }
    }
    __syncthreads();

    auto issue = [&](int t) {                  // one thread: expect_tx + 2 TMA
        const int s = t % 3;
        const unsigned mb = FULL + s * 8;
        asm volatile("mbarrier.arrive.expect_tx.shared.b64 _, [%0], %1;"
                     :: "r"(mb), "r"((unsigned)STG) : "memory");
        asm volatile(
            "cp.async.bulk.tensor.2d.shared::cta.global.tile.mbarrier::complete_tx::bytes "
            "[%0], [%1, {%2, %3}], [%4];"
            :: "r"(sbase + s * STG), "l"(&tma_a), "r"(t * 64), "r"(bm0), "r"(mb)
            : "memory");
        asm volatile(
            "cp.async.bulk.tensor.2d.shared::cta.global.tile.mbarrier::complete_tx::bytes "
            "[%0], [%1, {%2, %3}], [%4];"
            :: "r"(sbase + s * STG + ASZ), "l"(&tma_b), "r"(t * 64), "r"(bn0), "r"(mb)
            : "memory");
    };
    if (tid == 0) { issue(0); issue(1); issue(2); }

    float acc[4][8][4];
    #pragma unroll
    for (int i = 0; i < 4; i++)
        #pragma unroll
        for (int j = 0; j < 8; j++)
            #pragma unroll
            for (int q = 0; q < 4; q++) acc[i][j][q] = 0.0f;

    const int arow = lane & 15;
    const int asel = lane >> 4;
    const int bg   = lane >> 3;                  // 0..3
    const int r = lane >> 2;
    const int c = lane & 3;

    #pragma unroll 1
    for (int t = 0; t < NSTG; t++) {
        const int s = t % 3;
        const unsigned par = (unsigned)((t / 3) & 1);
        mbar_wait(FULL + s * 8, par);            // own data dependency only

        const unsigned As = sbase + s * STG;
        const unsigned Bs = As + ASZ;

        #pragma unroll
        for (int ks = 0; ks < 4; ks++) {         // 4 x k16 steps = 64 k
            unsigned a[4][4], b[8][2];
            #pragma unroll
            for (int mt = 0; mt < 4; mt++) {
                const int row = wm * 64 + mt * 16 + arow;
                const int ch  = 2 * ks + asel;
                ldsm_x4(a[mt], As + row * 128 + ((ch ^ (row & 7)) * 16));
            }
            #pragma unroll
            for (int p = 0; p < 4; p++) {        // each x4 fills frags 2p, 2p+1
                const int n  = wn * 64 + p * 16 + ((bg >> 1) << 3) + (lane & 7);
                const int ch = 2 * ks + (bg & 1);
                ldsm_x4(&b[2 * p][0], Bs + n * 128 + ((ch ^ (n & 7)) * 16));
            }
            #pragma unroll
            for (int mt = 0; mt < 4; mt++)
                #pragma unroll
                for (int nt = 0; nt < 8; nt++)
                    mma_f16(acc[mt][nt], a[mt], b[nt]);
        }

        __syncwarp();
        if (lane == 0) mbar_arrive(EMPTY + s * 8);   // warp done reading buffer s

        if (tid == 0 && t + 3 < NSTG) {
            mbar_wait(EMPTY + s * 8, par);           // all 4 warps released s
            issue(t + 3);                            // reuse buffer s
        }
    }

    // ---- epilogue: streaming stores (keep A/B resident in L2) ----
    #pragma unroll
    for (int mt = 0; mt < 4; mt++) {
        #pragma unroll
        for (int nt = 0; nt < 8; nt++) {
            const int row = bm0 + wm * 64 + mt * 16 + r;
            const int col = bn0 + wn * 64 + nt * 8 + c * 2;
            float* p = out + (size_t)row * ODIM + col;
            __stcs((float2*)p, make_float2(acc[mt][nt][0], acc[mt][nt][1]));
            __stcs((float2*)(p + (size_t)8 * ODIM),
                   make_float2(acc[mt][nt][2], acc[mt][nt][3]));
        }
    }
}

// Driver entry point fetched through cudart (no -lcuda needed at link time)
typedef CUresult (*PFN_encodeTiled)(
    CUtensorMap*, CUtensorMapDataType, cuuint32_t, void*,
    const cuuint64_t*, const cuuint64_t*, const cuuint32_t*, const cuuint32_t*,
    CUtensorMapInterleave, CUtensorMapSwizzle, CUtensorMapL2promotion,
    CUtensorMapFloatOOBfill);

extern "C" void kernel_launch(void* const* d_in, const int* in_sizes, int n_in,
                              void* d_out, int out_size) {
    const float* x       = (const float*)d_in[0];
    const int*   qweight = (const int*)d_in[1];
    const float* scales  = (const float*)d_in[2];
    const int*   qzeros  = (const int*)d_in[3];
    float*       out     = (float*)d_out;

    const int M = in_sizes[0] / KDIM;            // 4096

    cvt_x<<<(M * KDIM) / (256 * 4), 256>>>(x);
    dequant_w<<<dim3(KW / 32, 32), 256>>>(qweight, scales, qzeros);

    static CUtensorMap tma_a, tma_b;
    static bool built = false;
    if (!built) {
        PFN_encodeTiled encode = nullptr;
        cudaDriverEntryPointQueryResult qr;
#if CUDART_VERSION >= 12050
        cudaGetDriverEntryPointByVersion("cuTensorMapEncodeTiled",
                                         (void**)&encode, 12000,
                                         cudaEnableDefault, &qr);
#else
        cudaGetDriverEntryPoint("cuTensorMapEncodeTiled",
                                (void**)&encode, cudaEnableDefault, &qr);
#endif
        void *pa = nullptr, *pb = nullptr;
        cudaGetSymbolAddress(&pa, g_x16);
        cudaGetSymbolAddress(&pb, g_w16);
        cuuint64_t dims_a[2] = {(cuuint64_t)KDIM, (cuuint64_t)M};
        cuuint64_t dims_b[2] = {(cuuint64_t)KDIM, (cuuint64_t)ODIM};
        cuuint64_t strides[1] = {(cuuint64_t)KDIM * 2};
        cuuint32_t box[2] = {64, 128};
        cuuint32_t es[2] = {1, 1};
        encode(&tma_a, CU_TENSOR_MAP_DATA_TYPE_UINT16, 2, pa,
               dims_a, strides, box, es,
               CU_TENSOR_MAP_INTERLEAVE_NONE, CU_TENSOR_MAP_SWIZZLE_128B,
               CU_TENSOR_MAP_L2_PROMOTION_L2_128B, CU_TENSOR_MAP_FLOAT_OOB_FILL_NONE);
        encode(&tma_b, CU_TENSOR_MAP_DATA_TYPE_UINT16, 2, pb,
               dims_b, strides, box, es,
               CU_TENSOR_MAP_INTERLEAVE_NONE, CU_TENSOR_MAP_SWIZZLE_128B,
               CU_TENSOR_MAP_L2_PROMOTION_L2_128B, CU_TENSOR_MAP_FLOAT_OOB_FILL_NONE);
        built = true;
    }

    cudaFuncSetAttribute(w4_hgemm, cudaFuncAttributeMaxDynamicSharedMemorySize,
                         SMEM_TOTAL);
    dim3 grid(M / BM, ODIM / BN);                // (32, 86) — bm fast
    w4_hgemm<<<grid, 128, SMEM_TOTAL>>>(tma_a, tma_b, out);
}